// round 3
// baseline (speedup 1.0000x reference)
#include <cuda_runtime.h>

// SSIM loss, single fused kernel (last-block finalize), f32x2-packed blurs.
// Shapes fixed: (16,31,256,256) fp32 x2 inputs, scalar fp32 out.

#define IMG   256
#define OUT   246          // 256 - 11 + 1
#define TW    32
#define TH    64
#define HALO  10
#define IN_W  42           // TW + HALO
#define IN_H  74           // TH + HALO
#define PADX  44           // u64 row stride, packed input tile
#define PADH  36           // row stride, moment arrays
#define NIMG  496
#define GX    8
#define GY    4
#define NBLOCKS (GX * GY * NIMG)   // 15872
#define NTOT  30015936.0   // 496 * 246 * 246

#define SXY_B  (IN_H * PADX * 8)             // 26048
#define HM_B   (IN_H * PADH * 8)             // 21312
#define HM4_B  (IN_H * PADH * 4)             // 10656
#define SMEM_B (SXY_B + 2 * HM_B + HM4_B)    // 79328

typedef unsigned long long u64;

__device__ constexpr float GW[11] = {
    0.00102838f, 0.00759874f, 0.03600078f, 0.10936071f, 0.21300555f,
    0.26601174f,
    0.21300555f, 0.10936071f, 0.03600078f, 0.00759874f, 0.00102838f
};

#define C1 1.0e-4f
#define C2 9.0e-4f

// ---- packed f32x2 helpers ----
__device__ __forceinline__ u64 pk2(float x, float y) {
    u64 r; asm("mov.b64 %0, {%1, %2};" : "=l"(r) : "f"(x), "f"(y)); return r;
}
__device__ __forceinline__ void unpk(u64 p, float& x, float& y) {
    asm("mov.b64 {%0, %1}, %2;" : "=f"(x), "=f"(y) : "l"(p));
}
__device__ __forceinline__ u64 f2fma(u64 a, u64 b, u64 c) {
    u64 d; asm("fma.rn.f32x2 %0, %1, %2, %3;" : "=l"(d) : "l"(a), "l"(b), "l"(c)); return d;
}
__device__ __forceinline__ u64 f2mul(u64 a, u64 b) {
    u64 d; asm("mul.rn.f32x2 %0, %1, %2;" : "=l"(d) : "l"(a), "l"(b)); return d;
}

__device__ double   g_acc;      // zero-init; each call leaves it back at 0
__device__ unsigned g_ticket;   // wraps back to 0 every call

__global__ __launch_bounds__(256)
void ssim_main_kernel(const float* __restrict__ X, const float* __restrict__ Y,
                      float* __restrict__ out) {
    extern __shared__ __align__(16) unsigned char dsm[];
    u64   (*sxy )[PADX] = (u64  (*)[PADX]) dsm;
    u64   (*hm01)[PADH] = (u64  (*)[PADH])(dsm + SXY_B);
    u64   (*hm23)[PADH] = (u64  (*)[PADH])(dsm + SXY_B + HM_B);
    float (*hm4 )[PADH] = (float(*)[PADH])(dsm + SXY_B + 2 * HM_B);
    __shared__ float red[8];

    const int tid = threadIdx.x;
    const int C0  = blockIdx.x * TW;
    const int R0  = blockIdx.y * TH;
    const int img = blockIdx.z;

    const float* __restrict__ xi = X + (size_t)img * IMG * IMG;
    const float* __restrict__ yi = Y + (size_t)img * IMG * IMG;

    u64 W2[11];
    #pragma unroll
    for (int k = 0; k < 11; k++) W2[k] = pk2(GW[k], GW[k]);

    // ---- Phase 1: haloed tile load, float4 pairs -> packed {x,y}. 74 rows x 11 groups.
    for (int i = tid; i < IN_H * 11; i += 256) {
        const int r = i / 11, g = i - r * 11;
        const int gr = R0 + r, gc = C0 + 4 * g;
        float4 xv = make_float4(0.f, 0.f, 0.f, 0.f);
        float4 yv = make_float4(0.f, 0.f, 0.f, 0.f);
        if (gr < IMG) {
            const int base = gr * IMG + gc;
            if (gc + 3 < IMG) {
                xv = *(const float4*)&xi[base];
                yv = *(const float4*)&yi[base];
            } else if (gc < IMG) {
                float* xp = &xv.x; float* yp = &yv.x;
                for (int t = 0; t < 4; t++)
                    if (gc + t < IMG) { xp[t] = xi[base + t]; yp[t] = yi[base + t]; }
            }
        }
        ulonglong2 p0 = make_ulonglong2(pk2(xv.x, yv.x), pk2(xv.y, yv.y));
        ulonglong2 p1 = make_ulonglong2(pk2(xv.z, yv.z), pk2(xv.w, yv.w));
        *(ulonglong2*)&sxy[r][4 * g]     = p0;
        *(ulonglong2*)&sxy[r][4 * g + 2] = p1;
    }
    __syncthreads();

    // ---- Phase 2: horizontal blur. 74 rows x 8 runs of 4 outputs = 592 runs.
    for (int i = tid; i < IN_H * (TW / 4); i += 256) {
        const int r  = i >> 3;
        const int c0 = (i & 7) * 4;

        u64 p[14];
        {
            const ulonglong2* src = (const ulonglong2*)&sxy[r][c0];
            #pragma unroll
            for (int j = 0; j < 7; j++) {
                ulonglong2 t = src[j];
                p[2 * j] = t.x; p[2 * j + 1] = t.y;
            }
        }

        u64  a0 = 0, a1 = 0, a2 = 0, a3 = 0;            // {hx,hy}
        u64  b0 = 0, b1 = 0, b2 = 0, b3 = 0;            // {hxx,hyy}
        float s0 = 0.f, s1 = 0.f, s2 = 0.f, s3 = 0.f;   // hxy
        #pragma unroll
        for (int k = 0; k < 14; k++) {
            float xk, yk; unpk(p[k], xk, yk);
            u64   sq = f2mul(p[k], p[k]);
            float xy = xk * yk;
            if (k <= 10)           { a0 = f2fma(p[k], W2[k],     a0); b0 = f2fma(sq, W2[k],     b0); s0 += GW[k]     * xy; }
            if (k >= 1 && k <= 11) { a1 = f2fma(p[k], W2[k - 1], a1); b1 = f2fma(sq, W2[k - 1], b1); s1 += GW[k - 1] * xy; }
            if (k >= 2 && k <= 12) { a2 = f2fma(p[k], W2[k - 2], a2); b2 = f2fma(sq, W2[k - 2], b2); s2 += GW[k - 2] * xy; }
            if (k >= 3)            { a3 = f2fma(p[k], W2[k - 3], a3); b3 = f2fma(sq, W2[k - 3], b3); s3 += GW[k - 3] * xy; }
        }

        *(ulonglong2*)&hm01[r][c0]     = make_ulonglong2(a0, a1);
        *(ulonglong2*)&hm01[r][c0 + 2] = make_ulonglong2(a2, a3);
        *(ulonglong2*)&hm23[r][c0]     = make_ulonglong2(b0, b1);
        *(ulonglong2*)&hm23[r][c0 + 2] = make_ulonglong2(b2, b3);
        *(float4*)&hm4[r][c0] = make_float4(s0, s1, s2, s3);
    }
    __syncthreads();

    // ---- Phase 3: vertical blur (streaming, 8-output runs) + SSIM.
    const int c  = tid & 31;
    const int r0 = (tid >> 5) * 8;   // 0..56

    u64 acc01[8], acc23[8];
    float acc4[8];
    #pragma unroll
    for (int j = 0; j < 8; j++) { acc01[j] = 0; acc23[j] = 0; acc4[j] = 0.f; }

    #pragma unroll
    for (int k = 0; k < 18; k++) {
        u64 v = hm01[r0 + k][c];
        #pragma unroll
        for (int j = 0; j < 8; j++)
            if (k - j >= 0 && k - j <= 10) acc01[j] = f2fma(v, W2[k - j], acc01[j]);
    }
    #pragma unroll
    for (int k = 0; k < 18; k++) {
        u64 v = hm23[r0 + k][c];
        #pragma unroll
        for (int j = 0; j < 8; j++)
            if (k - j >= 0 && k - j <= 10) acc23[j] = f2fma(v, W2[k - j], acc23[j]);
    }
    #pragma unroll
    for (int k = 0; k < 18; k++) {
        float v = hm4[r0 + k][c];
        #pragma unroll
        for (int j = 0; j < 8; j++)
            if (k - j >= 0 && k - j <= 10) acc4[j] += GW[k - j] * v;
    }

    float lsum = 0.f;
    const int oc = C0 + c;
    #pragma unroll
    for (int j = 0; j < 8; j++) {
        int orow = R0 + r0 + j;
        if (orow < OUT && oc < OUT) {
            float mx, my;   unpk(acc01[j], mx, my);
            float mxx, myy; unpk(acc23[j], mxx, myy);
            float mxy = acc4[j];
            float vx  = mxx - mx * mx;
            float vy  = myy - my * my;
            float cov = mxy - mx * my;
            float num = (2.f * mx * my + C1) * (2.f * cov + C2);
            float den = (mx * mx + my * my + C1) * (vx + vy + C2);
            lsum += __fdividef(num, den);
        }
    }

    // ---- block reduce -> global accumulator; last block finalizes + resets
    #pragma unroll
    for (int o = 16; o > 0; o >>= 1)
        lsum += __shfl_xor_sync(0xffffffffu, lsum, o);
    if ((tid & 31) == 0) red[tid >> 5] = lsum;
    __syncthreads();
    if (tid == 0) {
        float s = 0.f;
        #pragma unroll
        for (int w = 0; w < 8; w++) s += red[w];
        atomicAdd(&g_acc, (double)s);
        __threadfence();
        unsigned t = atomicInc(&g_ticket, NBLOCKS - 1);
        if (t == NBLOCKS - 1) {
            double tot = atomicAdd(&g_acc, 0.0);   // coherent read
            out[0] = (float)(1.0 - tot / NTOT);
            atomicExch((unsigned long long*)&g_acc, 0ull);  // reset for next call
        }
    }
}

extern "C" void kernel_launch(void* const* d_in, const int* in_sizes, int n_in,
                              void* d_out, int out_size) {
    const float* X = (const float*)d_in[0];
    const float* Y = (const float*)d_in[1];
    float* out = (float*)d_out;

    static bool attr_set = false;
    if (!attr_set) {
        cudaFuncSetAttribute(ssim_main_kernel,
                             cudaFuncAttributeMaxDynamicSharedMemorySize, SMEM_B);
        attr_set = true;
    }

    dim3 grid(GX, GY, NIMG);   // 8 x 4 x 496
    ssim_main_kernel<<<grid, 256, SMEM_B>>>(X, Y, out);
}

// round 6
// speedup vs baseline: 1.4154x; 1.4154x over previous
#include <cuda_runtime.h>

// SSIM loss, single fused kernel, f32x2-packed blurs, GMEM-direct horizontal pass.
// Shapes fixed: (16,31,256,256) fp32 x2 inputs, scalar fp32 out.

#define IMG   256
#define OUT   246          // 256 - 11 + 1
#define TW    32
#define TH    64
#define HALO  10
#define IN_H  74           // TH + HALO
#define PADH  36           // row stride (elems), moment arrays
#define NIMG  496
#define GX    8
#define GY    4
#define NBLOCKS (GX * GY * NIMG)   // 15872
#define NTOT  30015936.0   // 496 * 246 * 246

#define HM_B   (IN_H * PADH * 8)             // 21312
#define HM4_B  (IN_H * PADH * 4)             // 10656
#define SMEM_B (2 * HM_B + HM4_B)            // 53280

typedef unsigned long long u64;

__device__ constexpr float GW[11] = {
    0.00102838f, 0.00759874f, 0.03600078f, 0.10936071f, 0.21300555f,
    0.26601174f,
    0.21300555f, 0.10936071f, 0.03600078f, 0.00759874f, 0.00102838f
};

#define C1 1.0e-4f
#define C2 9.0e-4f

// ---- packed f32x2 helpers ----
__device__ __forceinline__ u64 pk2(float x, float y) {
    u64 r; asm("mov.b64 %0, {%1, %2};" : "=l"(r) : "f"(x), "f"(y)); return r;
}
__device__ __forceinline__ void unpk(u64 p, float& x, float& y) {
    asm("mov.b64 {%0, %1}, %2;" : "=f"(x), "=f"(y) : "l"(p));
}
__device__ __forceinline__ u64 f2fma(u64 a, u64 b, u64 c) {
    u64 d; asm("fma.rn.f32x2 %0, %1, %2, %3;" : "=l"(d) : "l"(a), "l"(b), "l"(c)); return d;
}
__device__ __forceinline__ u64 f2mul(u64 a, u64 b) {
    u64 d; asm("mul.rn.f32x2 %0, %1, %2;" : "=l"(d) : "l"(a), "l"(b)); return d;
}

__device__ double   g_acc;      // zero-init; each call leaves it back at 0
__device__ unsigned g_ticket;   // wraps back to 0 every call

__global__ __launch_bounds__(256, 4)
void ssim_main_kernel(const float* __restrict__ X, const float* __restrict__ Y,
                      float* __restrict__ out) {
    extern __shared__ __align__(16) unsigned char dsm[];
    u64   (*hm01)[PADH] = (u64  (*)[PADH]) dsm;
    u64   (*hm23)[PADH] = (u64  (*)[PADH])(dsm + HM_B);
    float (*hm4 )[PADH] = (float(*)[PADH])(dsm + 2 * HM_B);
    __shared__ float red[8];

    const int tid = threadIdx.x;
    const int C0  = blockIdx.x * TW;
    const int R0  = blockIdx.y * TH;
    const int img = blockIdx.z;

    const float* __restrict__ xi = X + (size_t)img * IMG * IMG;
    const float* __restrict__ yi = Y + (size_t)img * IMG * IMG;

    u64 W2[11];
    #pragma unroll
    for (int k = 0; k < 11; k++) W2[k] = pk2(GW[k], GW[k]);

    // ---- Phase 1: horizontal blur straight from GMEM. 74 rows x 8 runs of 4 outputs.
    for (int i = tid; i < IN_H * 8; i += 256) {
        const int r  = i >> 3;
        const int c0 = (i & 7) * 4;
        const int gr = R0 + r;
        const int gc = C0 + c0;          // multiple of 4 -> 16B aligned

        float xv[16], yv[16];
        if (gr < IMG) {
            const float* __restrict__ xr = xi + gr * IMG + gc;
            const float* __restrict__ yr = yi + gr * IMG + gc;
            #pragma unroll
            for (int q = 0; q < 4; q++) {
                const int b = 4 * q;
                if (gc + b + 3 < IMG) {
                    float4 a = *(const float4*)(xr + b);
                    xv[b] = a.x; xv[b + 1] = a.y; xv[b + 2] = a.z; xv[b + 3] = a.w;
                    float4 d = *(const float4*)(yr + b);
                    yv[b] = d.x; yv[b + 1] = d.y; yv[b + 2] = d.z; yv[b + 3] = d.w;
                } else {
                    #pragma unroll
                    for (int t = 0; t < 4; t++) {
                        bool ok = (gc + b + t < IMG);
                        xv[b + t] = ok ? xr[b + t] : 0.f;
                        yv[b + t] = ok ? yr[b + t] : 0.f;
                    }
                }
            }
        } else {
            #pragma unroll
            for (int t = 0; t < 16; t++) { xv[t] = 0.f; yv[t] = 0.f; }
        }

        u64 p[14];
        #pragma unroll
        for (int k = 0; k < 14; k++) p[k] = pk2(xv[k], yv[k]);

        u64  a0 = 0, a1 = 0, a2 = 0, a3 = 0;            // {hx,hy}
        u64  b0 = 0, b1 = 0, b2 = 0, b3 = 0;            // {hxx,hyy}
        float s0 = 0.f, s1 = 0.f, s2 = 0.f, s3 = 0.f;   // hxy
        #pragma unroll
        for (int k = 0; k < 14; k++) {
            u64   sq = f2mul(p[k], p[k]);
            float xy = xv[k] * yv[k];
            if (k <= 10)           { a0 = f2fma(p[k], W2[k],     a0); b0 = f2fma(sq, W2[k],     b0); s0 += GW[k]     * xy; }
            if (k >= 1 && k <= 11) { a1 = f2fma(p[k], W2[k - 1], a1); b1 = f2fma(sq, W2[k - 1], b1); s1 += GW[k - 1] * xy; }
            if (k >= 2 && k <= 12) { a2 = f2fma(p[k], W2[k - 2], a2); b2 = f2fma(sq, W2[k - 2], b2); s2 += GW[k - 2] * xy; }
            if (k >= 3)            { a3 = f2fma(p[k], W2[k - 3], a3); b3 = f2fma(sq, W2[k - 3], b3); s3 += GW[k - 3] * xy; }
        }

        *(ulonglong2*)&hm01[r][c0]     = make_ulonglong2(a0, a1);
        *(ulonglong2*)&hm01[r][c0 + 2] = make_ulonglong2(a2, a3);
        *(ulonglong2*)&hm23[r][c0]     = make_ulonglong2(b0, b1);
        *(ulonglong2*)&hm23[r][c0 + 2] = make_ulonglong2(b2, b3);
        *(float4*)&hm4[r][c0] = make_float4(s0, s1, s2, s3);
    }
    __syncthreads();

    // ---- Phase 2: vertical blur (streaming, 8-output runs) + SSIM.
    const int c  = tid & 31;
    const int r0 = (tid >> 5) * 8;   // 0..56

    u64 acc01[8], acc23[8];
    float acc4[8];
    #pragma unroll
    for (int j = 0; j < 8; j++) { acc01[j] = 0; acc23[j] = 0; acc4[j] = 0.f; }

    #pragma unroll
    for (int k = 0; k < 18; k++) {
        u64 v = hm01[r0 + k][c];
        #pragma unroll
        for (int j = 0; j < 8; j++)
            if (k - j >= 0 && k - j <= 10) acc01[j] = f2fma(v, W2[k - j], acc01[j]);
    }
    #pragma unroll
    for (int k = 0; k < 18; k++) {
        u64 v = hm23[r0 + k][c];
        #pragma unroll
        for (int j = 0; j < 8; j++)
            if (k - j >= 0 && k - j <= 10) acc23[j] = f2fma(v, W2[k - j], acc23[j]);
    }
    #pragma unroll
    for (int k = 0; k < 18; k++) {
        float v = hm4[r0 + k][c];
        #pragma unroll
        for (int j = 0; j < 8; j++)
            if (k - j >= 0 && k - j <= 10) acc4[j] += GW[k - j] * v;
    }

    float lsum = 0.f;
    const int oc = C0 + c;
    #pragma unroll
    for (int j = 0; j < 8; j++) {
        int orow = R0 + r0 + j;
        if (orow < OUT && oc < OUT) {
            float mx, my;   unpk(acc01[j], mx, my);
            float mxx, myy; unpk(acc23[j], mxx, myy);
            float mxy = acc4[j];
            float vx  = mxx - mx * mx;
            float vy  = myy - my * my;
            float cov = mxy - mx * my;
            float num = (2.f * mx * my + C1) * (2.f * cov + C2);
            float den = (mx * mx + my * my + C1) * (vx + vy + C2);
            lsum += __fdividef(num, den);
        }
    }

    // ---- block reduce -> global accumulator; last block finalizes + resets
    #pragma unroll
    for (int o = 16; o > 0; o >>= 1)
        lsum += __shfl_xor_sync(0xffffffffu, lsum, o);
    if ((tid & 31) == 0) red[tid >> 5] = lsum;
    __syncthreads();
    if (tid == 0) {
        float s = 0.f;
        #pragma unroll
        for (int w = 0; w < 8; w++) s += red[w];
        atomicAdd(&g_acc, (double)s);
        __threadfence();
        unsigned t = atomicInc(&g_ticket, NBLOCKS - 1);
        if (t == NBLOCKS - 1) {
            double tot = atomicAdd(&g_acc, 0.0);   // coherent read
            out[0] = (float)(1.0 - tot / NTOT);
            atomicExch((unsigned long long*)&g_acc, 0ull);  // reset for next call
        }
    }
}

extern "C" void kernel_launch(void* const* d_in, const int* in_sizes, int n_in,
                              void* d_out, int out_size) {
    const float* X = (const float*)d_in[0];
    const float* Y = (const float*)d_in[1];
    float* out = (float*)d_out;

    cudaFuncSetAttribute(ssim_main_kernel,
                         cudaFuncAttributeMaxDynamicSharedMemorySize, SMEM_B);

    dim3 grid(GX, GY, NIMG);   // 8 x 4 x 496
    ssim_main_kernel<<<grid, 256, SMEM_B>>>(X, Y, out);
}